// round 11
// baseline (speedup 1.0000x reference)
#include <cuda_runtime.h>
#include <cuda_fp16.h>
#include <cstdint>

// GPTQ 4-bit: pre-dequant to fp16 scratch, then warp-specialized HMMA GEMM.
// Pass 1: xh = fp16(x)                 [M,K]  (64 MB)
// Pass 2: wt = fp16(s*(w4-(z4+1)))^T   [N,K]  (90 MB)
// Pass 3: out = xh @ wt^T, mma.sync m16n8k16, fp32 accum.
// R11: producer/consumer warp specialization over an mbarrier-paced 6-stage
//      cp.async ring. 16 consumer warps (warp tile 64x32, R5 shape) never
//      rendezvous with each other; 2 producer warps own all cp.async and
//      publish stages via cp.async.mbarrier.arrive.noinc.

#define M_DIM 8192
#define N_DIM 11008
#define K_DIM 4096
#define BM 256
#define BN 128
#define BK 32
#define CHUNKS (K_DIM / BK)          // 128
#define ROWB 80                      // 32 halves (64B) + 16B pad per smem row
#define A_BYTES (BM * ROWB)          // 20480
#define B_BYTES (BN * ROWB)          // 10240
#define STAGEB (A_BYTES + B_BYTES)   // 30720
#define STAGES 6
#define MBAR_BASE (STAGES * STAGEB)          // 184320
#define SMEM_TOTAL (MBAR_BASE + 16 * 8)      // 184448
#define CONSUMERS 512
#define PRODUCERS 64
#define THREADS (CONSUMERS + PRODUCERS)      // 576

__device__ __half g_xh[(size_t)M_DIM * K_DIM];   // 64 MB scratch
__device__ __half g_wt[(size_t)N_DIM * K_DIM];   // 90 MB scratch

__device__ __forceinline__ uint32_t smem_u32(const void* p) {
    uint32_t a;
    asm("{ .reg .u64 t; cvta.to.shared.u64 t, %1; cvt.u32.u64 %0, t; }"
        : "=r"(a) : "l"(p));
    return a;
}

#define LDMX4(r, addr)                                                       \
    asm volatile("ldmatrix.sync.aligned.m8n8.x4.shared.b16 {%0,%1,%2,%3}, [%4];" \
        : "=r"((r)[0]), "=r"((r)[1]), "=r"((r)[2]), "=r"((r)[3]) : "r"(addr))

#define MMA16816(d, a, b0, b1)                                               \
    asm volatile("mma.sync.aligned.m16n8k16.row.col.f32.f16.f16.f32 "        \
        "{%0,%1,%2,%3}, {%4,%5,%6,%7}, {%8,%9}, {%0,%1,%2,%3};"              \
        : "+f"((d)[0]), "+f"((d)[1]), "+f"((d)[2]), "+f"((d)[3])             \
        : "r"((a)[0]), "r"((a)[1]), "r"((a)[2]), "r"((a)[3]), "r"(b0), "r"(b1))

#define CP16(dst, src)                                                       \
    asm volatile("cp.async.cg.shared.global [%0], [%1], 16;"                 \
        :: "r"(dst), "l"(src) : "memory")

// async arrive: fires one arrival on mbar when this thread's prior cp.asyncs land
#define CP_MBAR_ARRIVE(mbar)                                                 \
    asm volatile("cp.async.mbarrier.arrive.noinc.shared.b64 [%0];"           \
        :: "r"(mbar) : "memory")

#define MBAR_INIT(addr, cnt) \
    asm volatile("mbarrier.init.shared.b64 [%0], %1;" :: "r"(addr), "r"(cnt) : "memory")
#define MBAR_ARRIVE(addr) \
    asm volatile("mbarrier.arrive.shared.b64 _, [%0];" :: "r"(addr) : "memory")

#define MBAR_WAIT(addr, parity) do {                                              \
    uint32_t _m = (addr), _p = (parity), _d;                                      \
    asm volatile("{\n\t.reg .pred p;\n\t"                                         \
        "mbarrier.try_wait.parity.shared.b64 p, [%1], %2;\n\t"                    \
        "selp.b32 %0, 1, 0, p;\n\t}" : "=r"(_d) : "r"(_m), "r"(_p) : "memory");   \
    if (!_d) {                                                                    \
        asm volatile("{\n\t.reg .pred P1;\n\t"                                    \
            "W_%=:\n\t"                                                           \
            "mbarrier.try_wait.parity.shared.b64 P1, [%0], %1;\n\t"               \
            "@P1 bra.uni D_%=;\n\t"                                               \
            "bra.uni W_%=;\n\t"                                                   \
            "D_%=:\n\t}" :: "r"(_m), "r"(_p) : "memory");                         \
    }                                                                             \
} while (0)

__device__ __forceinline__ uint32_t pack2(float a, float b) {
    __half2 h = __float22half2_rn(make_float2(a, b));
    return *reinterpret_cast<uint32_t*>(&h);
}

// ---------- pass 1: x fp32 -> fp16 ----------
__global__ __launch_bounds__(256) void cvt_x_kernel(const float* __restrict__ x) {
    const size_t i = ((size_t)blockIdx.x * 256 + threadIdx.x) * 8;
    const float4 a = *reinterpret_cast<const float4*>(x + i);
    const float4 b = *reinterpret_cast<const float4*>(x + i + 4);
    uint4 o;
    o.x = pack2(a.x, a.y); o.y = pack2(a.z, a.w);
    o.z = pack2(b.x, b.y); o.w = pack2(b.z, b.w);
    *reinterpret_cast<uint4*>(g_xh + i) = o;
}

// ---------- pass 2: dequant to W^T fp16 [N,K] ----------
__global__ __launch_bounds__(256) void dequant_kernel(const int* __restrict__ qweight,
                                                      const float* __restrict__ scales,
                                                      const int* __restrict__ qzeros) {
    const int n  = blockIdx.x * 256 + threadIdx.x;     // 0..11007
    const int kw = blockIdx.y;                          // 0..511 (k-word)
    const int g  = kw >> 4;                             // group = (kw*8)/128
    const float s = scales[(size_t)g * N_DIM + n];
    const unsigned qz = (unsigned)qzeros[(size_t)g * (N_DIM / 8) + (n >> 3)];
    const float neg = -s * (float)(((qz >> ((n & 7) * 4)) & 0xFu) + 1u);
    const unsigned q = (unsigned)qweight[(size_t)kw * N_DIM + n];
    uint4 o;
    uint32_t* p = &o.x;
    #pragma unroll
    for (int j = 0; j < 4; j++) {
        const float f0 = fmaf(s, (float)((q >> (8 * j))     & 0xFu), neg);
        const float f1 = fmaf(s, (float)((q >> (8 * j + 4)) & 0xFu), neg);
        p[j] = pack2(f0, f1);
    }
    *reinterpret_cast<uint4*>(g_wt + (size_t)n * K_DIM + kw * 8) = o;
}

// ---------- nop: pads launch order so ncu (captures index 3) hits the GEMM ----------
__global__ void nop_kernel() {}

// ---------- pass 3: warp-specialized HMMA GEMM ----------
__global__ __launch_bounds__(THREADS, 1)
void hgemm_main(float* __restrict__ out)
{
    extern __shared__ __align__(16) char smem[];
    const uint32_t sb = smem_u32(smem);
    const int tid  = threadIdx.x;
    const int lane = tid & 31;
    const int wid  = tid >> 5;
    const int m0   = blockIdx.x * BM;
    const int n0   = blockIdx.y * BN;

    // mbarriers: full[s] at MBAR_BASE + s*8 (count=PRODUCERS, async arrivals),
    //            empty[s] at MBAR_BASE + 64 + s*8 (count=CONSUMERS)
    const uint32_t fullB  = sb + MBAR_BASE;
    const uint32_t emptyB = sb + MBAR_BASE + 64;
    if (tid == 0) {
        #pragma unroll
        for (int s = 0; s < STAGES; s++) {
            MBAR_INIT(fullB  + s * 8, PRODUCERS);
            MBAR_INIT(emptyB + s * 8, CONSUMERS);
        }
    }
    __syncthreads();

    if (wid >= 16) {
        // ================= PRODUCERS (warps 16-17, 64 threads) =================
        const int p = tid - CONSUMERS;   // 0..63
        // A: rows 4p..4p+3 (64B each); B: rows 2p..2p+1 (64B each)
        const __half* aSrcP = g_xh + (size_t)(m0 + 4 * p) * K_DIM;
        const __half* bSrcP = g_wt + (size_t)(n0 + 2 * p) * K_DIM;
        const uint32_t aDstP = sb + (uint32_t)(4 * p) * ROWB;
        const uint32_t bDstP = sb + (uint32_t)A_BYTES + (uint32_t)(2 * p) * ROWB;

        int s = 0, ep = 1;
        #pragma unroll 1
        for (int c = 0; c < CHUNKS; c++) {
            if (c >= STAGES) MBAR_WAIT(emptyB + s * 8, ep);
            const uint32_t base = (uint32_t)(s * STAGEB);
            const int koff = c * BK;
            #pragma unroll
            for (int i = 0; i < 4; i++) {
                const __half* src = aSrcP + (size_t)i * K_DIM + koff;
                const uint32_t dst = aDstP + base + i * ROWB;
                CP16(dst,      src);
                CP16(dst + 16, src + 8);
                CP16(dst + 32, src + 16);
                CP16(dst + 48, src + 24);
            }
            #pragma unroll
            for (int i = 0; i < 2; i++) {
                const __half* src = bSrcP + (size_t)i * K_DIM + koff;
                const uint32_t dst = bDstP + base + i * ROWB;
                CP16(dst,      src);
                CP16(dst + 16, src + 8);
                CP16(dst + 32, src + 16);
                CP16(dst + 48, src + 24);
            }
            CP_MBAR_ARRIVE(fullB + s * 8);
            if (++s == STAGES) { s = 0; ep ^= 1; }
        }
        return;   // producers done; consumers own the epilogue
    }

    // ================= CONSUMERS (warps 0-15) =================
    const int wm = wid & 3;
    const int wn = wid >> 2;
    const int lr  = lane & 15;
    const int lsB = (lane >> 4) * 16;
    const uint32_t aLd0 = sb + (uint32_t)((wm * 64 + lr) * ROWB) + lsB;
    const uint32_t bLd0 = sb + (uint32_t)(A_BYTES + (wn * 32 + lr) * ROWB) + lsB;

    float acc[4][4][4];
    #pragma unroll
    for (int i = 0; i < 4; i++)
        #pragma unroll
        for (int j = 0; j < 4; j++)
            #pragma unroll
            for (int e = 0; e < 4; e++) acc[i][j][e] = 0.0f;

    int s = 0, fp = 0;
    #pragma unroll 1
    for (int c = 0; c < CHUNKS; c++) {
        MBAR_WAIT(fullB + s * 8, fp);
        const uint32_t aLd = aLd0 + (uint32_t)(s * STAGEB);
        const uint32_t bLd = bLd0 + (uint32_t)(s * STAGEB);

        // ks0
        uint32_t a[4][4], b[2][4];
        #pragma unroll
        for (int mi = 0; mi < 4; mi++) LDMX4(a[mi], aLd + mi * 16 * ROWB);
        #pragma unroll
        for (int nj = 0; nj < 2; nj++) LDMX4(b[nj], bLd + nj * 16 * ROWB);
        #pragma unroll
        for (int nj = 0; nj < 2; nj++)
            #pragma unroll
            for (int mi = 0; mi < 4; mi++) {
                MMA16816(acc[mi][2 * nj],     a[mi], b[nj][0], b[nj][2]);
                MMA16816(acc[mi][2 * nj + 1], a[mi], b[nj][1], b[nj][3]);
            }

        // ks1
        #pragma unroll
        for (int mi = 0; mi < 4; mi++) LDMX4(a[mi], aLd + 32 + mi * 16 * ROWB);
        #pragma unroll
        for (int nj = 0; nj < 2; nj++) LDMX4(b[nj], bLd + 32 + nj * 16 * ROWB);
        // first half of ks1 MMAs (consumes ks1 frags -> all LDSM of stage done)
        #pragma unroll
        for (int mi = 0; mi < 4; mi++) {
            MMA16816(acc[mi][0], a[mi], b[0][0], b[0][2]);
            MMA16816(acc[mi][1], a[mi], b[0][1], b[0][3]);
        }
        MBAR_ARRIVE(emptyB + s * 8);   // stage free for producer reuse
        #pragma unroll
        for (int mi = 0; mi < 4; mi++) {
            MMA16816(acc[mi][2], a[mi], b[1][0], b[1][2]);
            MMA16816(acc[mi][3], a[mi], b[1][1], b[1][3]);
        }

        if (++s == STAGES) { s = 0; fp ^= 1; }
    }

    // epilogue
    #pragma unroll
    for (int mi = 0; mi < 4; mi++) {
        const int row = m0 + wm * 64 + mi * 16 + (lane >> 2);
        float* o0 = out + (size_t)row * N_DIM + n0 + wn * 32 + (lane & 3) * 2;
        float* o1 = o0 + (size_t)8 * N_DIM;
        #pragma unroll
        for (int j = 0; j < 4; j++) {
            *(float2*)(o0 + j * 8) = make_float2(acc[mi][j][0], acc[mi][j][1]);
            *(float2*)(o1 + j * 8) = make_float2(acc[mi][j][2], acc[mi][j][3]);
        }
    }
}

extern "C" void kernel_launch(void* const* d_in, const int* in_sizes, int n_in,
                              void* d_out, int out_size)
{
    const float* x       = (const float*)d_in[0];
    const int*   qweight = (const int*)  d_in[1];
    const float* scales  = (const float*)d_in[2];
    const int*   qzeros  = (const int*)  d_in[3];
    float* out = (float*)d_out;

    static bool attr_set = false;
    if (!attr_set) {
        cudaFuncSetAttribute(hgemm_main,
                             cudaFuncAttributeMaxDynamicSharedMemorySize, SMEM_TOTAL);
        attr_set = true;
    }

    cvt_x_kernel<<<(int)((size_t)M_DIM * K_DIM / 8 / 256), 256>>>(x);       // idx 0
    dequant_kernel<<<dim3(N_DIM / 256, K_DIM / 8), 256>>>(qweight, scales, qzeros); // idx 1
    nop_kernel<<<1, 32>>>();                                                // idx 2

    dim3 grid(M_DIM / BM, N_DIM / BN);   // (32, 86), m-fastest for L2 locality
    hgemm_main<<<grid, THREADS, SMEM_TOTAL>>>(out);                         // idx 3 -> ncu
}